// round 1
// baseline (speedup 1.0000x reference)
#include <cuda_runtime.h>

#define N_NODES 100000
#define E_MAX   3400000

// ---------------- scratch (device globals; no allocation allowed) ------------
__device__ int   g_cnt[N_NODES];
__device__ int   g_cursor[N_NODES];
__device__ float g_dinv[N_NODES];
__device__ int   g_rowptr[N_NODES + 1];
__device__ int   g_src[E_MAX];
__device__ int   g_dst[E_MAX];
__device__ int   g_csr[E_MAX];                       // src indices grouped by dst
__device__ __align__(16) float g_h1[(size_t)N_NODES * 128];
__device__ __align__(16) float g_a1[(size_t)N_NODES * 128];
__device__ __align__(16) float g_h2[(size_t)N_NODES * 64];
__device__ int   g_is64;

// ---------------- edge dtype detection (int64 vs silently-downcast int32) ---
__global__ void detect_kernel(const long long* __restrict__ edges) {
    __shared__ int bad;
    if (threadIdx.x == 0) bad = 0;
    __syncthreads();
    for (int i = threadIdx.x; i < 1024; i += blockDim.x) {
        long long v = edges[i];
        if (v < 0 || v >= N_NODES) bad = 1;   // benign race: all writers store 1
    }
    __syncthreads();
    if (threadIdx.x == 0) g_is64 = bad ? 0 : 1;
}

__global__ void init_kernel() {
    int i = blockIdx.x * blockDim.x + threadIdx.x;
    if (i < N_NODES) { g_cnt[i] = 0; g_cursor[i] = 0; }
}

__global__ void convert_kernel(const void* __restrict__ edges, int E) {
    int e = blockIdx.x * blockDim.x + threadIdx.x;
    if (e >= E) return;
    if (g_is64) {
        const long long* p = (const long long*)edges;
        g_src[e] = (int)p[e];
        g_dst[e] = (int)p[(size_t)E + e];
    } else {
        const int* p = (const int*)edges;
        g_src[e] = p[e];
        g_dst[e] = p[E + e];
    }
}

__global__ void count_kernel(int E) {
    int e = blockIdx.x * blockDim.x + threadIdx.x;
    if (e < E) atomicAdd(&g_cnt[g_dst[e]], 1);
}

__global__ void dinv_kernel() {
    int i = blockIdx.x * blockDim.x + threadIdx.x;
    if (i < N_NODES) g_dinv[i] = rsqrtf((float)(g_cnt[i] + 1));  // +1 = self loop
}

// single-block exclusive scan of g_cnt -> g_rowptr
__global__ void scan_kernel() {
    __shared__ int ssum[1024];
    const int n = N_NODES;
    int tid = threadIdx.x;
    const int per = (n + 1023) / 1024;
    int start = tid * per;
    int end = start + per; if (end > n) end = n;
    int s = 0;
    for (int i = start; i < end; i++) s += g_cnt[i];
    ssum[tid] = s;
    __syncthreads();
    for (int off = 1; off < 1024; off <<= 1) {
        int v = (tid >= off) ? ssum[tid - off] : 0;
        __syncthreads();
        ssum[tid] += v;
        __syncthreads();
    }
    int run = ssum[tid] - s;  // exclusive prefix of this chunk
    for (int i = start; i < end; i++) { g_rowptr[i] = run; run += g_cnt[i]; }
    if (tid == 1023) g_rowptr[n] = ssum[1023];
}

__global__ void fill_kernel(int E) {
    int e = blockIdx.x * blockDim.x + threadIdx.x;
    if (e >= E) return;
    int d = g_dst[e];
    int pos = g_rowptr[d] + atomicAdd(&g_cursor[d], 1);
    g_csr[pos] = g_src[e];
}

// ---------------- GEMM: Y[N, DOUT] = X[N,128] @ W[128, DOUT] ----------------
// W fully staged in SMEM; 32 rows/block, 8 warps, 4 rows/warp, DOUT/32 cols/lane.
template <int DOUT>
__global__ void gemm_kernel(const float* __restrict__ X, const float* __restrict__ W,
                            float* __restrict__ Y) {
    extern __shared__ float smem[];
    float* sW = smem;                // 128 * DOUT
    float* sX = smem + 128 * DOUT;   // 32 * 128
    int tid = threadIdx.x, wid = tid >> 5, lane = tid & 31;

    for (int i = tid * 4; i < 128 * DOUT; i += 1024)
        *(float4*)&sW[i] = *(const float4*)&W[i];
    int row0 = blockIdx.x * 32;
    for (int i = tid * 4; i < 32 * 128; i += 1024)
        *(float4*)&sX[i] = *(const float4*)&X[(size_t)row0 * 128 + i];
    __syncthreads();

    constexpr int V = DOUT / 32;     // 4 (DOUT=128) or 2 (DOUT=64)
    float acc[4][V];
#pragma unroll
    for (int r = 0; r < 4; r++)
#pragma unroll
        for (int c = 0; c < V; c++) acc[r][c] = 0.0f;

    int r0 = wid * 4;
#pragma unroll 4
    for (int k = 0; k < 128; k++) {
        float wv[V];
        if constexpr (V == 4) {
            float4 t = *(float4*)&sW[k * DOUT + lane * 4];
            wv[0] = t.x; wv[1] = t.y; wv[2] = t.z; wv[3] = t.w;
        } else {
            float2 t = *(float2*)&sW[k * DOUT + lane * 2];
            wv[0] = t.x; wv[1] = t.y;
        }
        float xv[4];
#pragma unroll
        for (int r = 0; r < 4; r++) xv[r] = sX[(r0 + r) * 128 + k];
#pragma unroll
        for (int r = 0; r < 4; r++)
#pragma unroll
            for (int c = 0; c < V; c++) acc[r][c] += xv[r] * wv[c];
    }

#pragma unroll
    for (int r = 0; r < 4; r++) {
        float* yp = &Y[(size_t)(row0 + r0 + r) * DOUT + lane * V];
        if constexpr (V == 4) *(float4*)yp = make_float4(acc[r][0], acc[r][1], acc[r][2], acc[r][3]);
        else                  *(float2*)yp = make_float2(acc[r][0], acc[r][1]);
    }
}

// ---------------- aggregation: one warp per destination node ----------------
// out[n] = dinv[n]*sum_{s in N(n)} dinv[s]*H[s] + dinv[n]^2*H[n] + bias  (opt relu)
template <int D, bool RELU>
__global__ void agg_kernel(const float* __restrict__ H, const float* __restrict__ bias,
                           float* __restrict__ OUT) {
    int gw = (blockIdx.x * blockDim.x + threadIdx.x) >> 5;
    if (gw >= N_NODES) return;
    int lane = threadIdx.x & 31;
    constexpr int V = D / 32;

    float acc[V];
#pragma unroll
    for (int c = 0; c < V; c++) acc[c] = 0.0f;

    int e = g_rowptr[gw], e1 = g_rowptr[gw + 1];
    for (; e < e1; e++) {
        int s = __ldg(&g_csr[e]);
        float w = __ldg(&g_dinv[s]);
        if constexpr (V == 4) {
            float4 hv = *(const float4*)&H[(size_t)s * D + lane * 4];
            acc[0] += w * hv.x; acc[1] += w * hv.y; acc[2] += w * hv.z; acc[3] += w * hv.w;
        } else {
            float2 hv = *(const float2*)&H[(size_t)s * D + lane * 2];
            acc[0] += w * hv.x; acc[1] += w * hv.y;
        }
    }

    float dd = g_dinv[gw];
    float dd2 = dd * dd;
    if constexpr (V == 4) {
        float4 hs = *(const float4*)&H[(size_t)gw * D + lane * 4];
        float4 bv = *(const float4*)&bias[lane * 4];
        float o0 = dd * acc[0] + dd2 * hs.x + bv.x;
        float o1 = dd * acc[1] + dd2 * hs.y + bv.y;
        float o2 = dd * acc[2] + dd2 * hs.z + bv.z;
        float o3 = dd * acc[3] + dd2 * hs.w + bv.w;
        if constexpr (RELU) {
            o0 = fmaxf(o0, 0.0f); o1 = fmaxf(o1, 0.0f);
            o2 = fmaxf(o2, 0.0f); o3 = fmaxf(o3, 0.0f);
        }
        *(float4*)&OUT[(size_t)gw * D + lane * 4] = make_float4(o0, o1, o2, o3);
    } else {
        float2 hs = *(const float2*)&H[(size_t)gw * D + lane * 2];
        float2 bv = *(const float2*)&bias[lane * 2];
        float o0 = dd * acc[0] + dd2 * hs.x + bv.x;
        float o1 = dd * acc[1] + dd2 * hs.y + bv.y;
        if constexpr (RELU) { o0 = fmaxf(o0, 0.0f); o1 = fmaxf(o1, 0.0f); }
        *(float2*)&OUT[(size_t)gw * D + lane * 2] = make_float2(o0, o1);
    }
}

// ---------------- launch -----------------------------------------------------
extern "C" void kernel_launch(void* const* d_in, const int* in_sizes, int n_in,
                              void* d_out, int out_size) {
    const float* x  = (const float*)d_in[0];
    const void*  ei = d_in[1];
    const float* W1 = (const float*)d_in[2];
    const float* b1 = (const float*)d_in[3];
    const float* W2 = (const float*)d_in[4];
    const float* b2 = (const float*)d_in[5];
    float* out = (float*)d_out;
    int E = in_sizes[1] / 2;   // element count of (2, E) regardless of int32/int64

    const int SMEM1 = (128 * 128 + 32 * 128) * 4;   // 80 KB
    const int SMEM2 = (128 * 64 + 32 * 128) * 4;    // 48 KB
    cudaFuncSetAttribute(gemm_kernel<128>, cudaFuncAttributeMaxDynamicSharedMemorySize, SMEM1);
    cudaFuncSetAttribute(gemm_kernel<64>,  cudaFuncAttributeMaxDynamicSharedMemorySize, SMEM2);

    float *h1, *a1, *h2;
    cudaGetSymbolAddress((void**)&h1, g_h1);
    cudaGetSymbolAddress((void**)&a1, g_a1);
    cudaGetSymbolAddress((void**)&h2, g_h2);

    const int TB = 256;
    int gE = (E + TB - 1) / TB;
    int gN = (N_NODES + TB - 1) / TB;

    detect_kernel<<<1, 256>>>((const long long*)ei);
    init_kernel<<<gN, TB>>>();
    convert_kernel<<<gE, TB>>>(ei, E);
    count_kernel<<<gE, TB>>>(E);
    dinv_kernel<<<gN, TB>>>();
    scan_kernel<<<1, 1024>>>();
    fill_kernel<<<gE, TB>>>(E);

    gemm_kernel<128><<<N_NODES / 32, 256, SMEM1>>>(x, W1, h1);
    agg_kernel<128, true><<<(N_NODES + 7) / 8, 256>>>(h1, b1, a1);
    gemm_kernel<64><<<N_NODES / 32, 256, SMEM2>>>(a1, W2, h2);
    agg_kernel<64, false><<<(N_NODES + 7) / 8, 256>>>(h2, b2, out);
}